// round 5
// baseline (speedup 1.0000x reference)
#include <cuda_runtime.h>
#include <math.h>

#define BB   64
#define TT   256
#define EE   256
#define HH   1024
#define H3   3072

// Scratch: input projections xw[dir][t][b][j] (includes input bias), ~402MB
__device__ float g_xw[(size_t)2 * TT * BB * H3];
// Hidden state ping-pong: [dir][parity][b][j]
__device__ float g_h[2][2][BB][HH];
// Grid barrier counters, one per direction (monotonic within a launch)
__device__ unsigned int g_bar[2];

// ---------------------------------------------------------------------------
// Packed f32x2 helpers (sm_103a FFMA2 path — ptxas never emits from C++)
// ---------------------------------------------------------------------------
typedef unsigned long long ull;

static __device__ __forceinline__ void fma2(ull& d, ull a, ull b) {
    asm("fma.rn.f32x2 %0, %1, %2, %0;" : "+l"(d) : "l"(a), "l"(b));
}
static __device__ __forceinline__ ull pack2(float x) {
    ull d;
    unsigned int u = __float_as_uint(x);
    asm("mov.b64 %0, {%1, %1};" : "=l"(d) : "r"(u));
    return d;
}
static __device__ __forceinline__ float2 unpack2(ull v) {
    unsigned int lo, hi;
    asm("mov.b64 {%0, %1}, %2;" : "=r"(lo), "=r"(hi) : "l"(v));
    float2 r; r.x = __uint_as_float(lo); r.y = __uint_as_float(hi);
    return r;
}

// ---------------------------------------------------------------------------
// Init hidden state for both directions + reset barrier counters
// ---------------------------------------------------------------------------
__global__ __launch_bounds__(256) void init_h_kernel(const float* __restrict__ hidden) {
    int i = blockIdx.x * blockDim.x + threadIdx.x;   // 0 .. 2*B*H-1
    if (i == 0) { g_bar[0] = 0u; g_bar[1] = 0u; }
    int dir = i / (BB * HH);
    int r   = i % (BB * HH);
    g_h[dir][0][r / HH][r % HH] = hidden[r];
}

// ---------------------------------------------------------------------------
// Fused embedding + input projection GEMM (FFMA2 inner loop):
//   xw[dir][t][b][j] = sum_e emb[x[b][t]][e] * W[e][j] + bi[j]
// M = T*B (row m = t*64+b), N = 3072, K = 256. Tile 64x64, K-chunk 32.
// ---------------------------------------------------------------------------
__global__ __launch_bounds__(256) void input_proj_kernel(
    const int* __restrict__ x, const float* __restrict__ emb,
    const float* __restrict__ Wf, const float* __restrict__ bf,
    const float* __restrict__ Wb, const float* __restrict__ bb)
{
    const int dir = blockIdx.z;
    const float* __restrict__ W  = dir ? Wb : Wf;
    const float* __restrict__ bi = dir ? bb : bf;   // row 0 of b = input bias

    const int m0 = blockIdx.y * 64;
    const int n0 = blockIdx.x * 64;

    __shared__ float sA[64][32];   // [m][k]
    __shared__ float sB[32][64];   // [k][n]
    __shared__ int   sRow[64];

    const int tid = threadIdx.x;
    if (tid < 64) {
        int m = m0 + tid;
        int t = m >> 6;
        int b = m & 63;
        sRow[tid] = x[b * TT + t];
    }
    __syncthreads();

    const int ty = tid >> 4;       // 0..15
    const int tx = tid & 15;       // 0..15

    ull acc2[4][2];
    #pragma unroll
    for (int i = 0; i < 4; i++) { acc2[i][0] = 0ull; acc2[i][1] = 0ull; }

    for (int k0 = 0; k0 < EE; k0 += 32) {
        #pragma unroll
        for (int r = 0; r < 2; r++) {
            int f  = tid + r * 256;        // 0..511
            int m  = f >> 3;               // 0..63
            int kc = (f & 7) * 4;          // 0..28
            float4 v = *(const float4*)&emb[(size_t)sRow[m] * EE + k0 + kc];
            *(float4*)&sA[m][kc] = v;
        }
        #pragma unroll
        for (int r = 0; r < 2; r++) {
            int f  = tid + r * 256;
            int kk = f >> 4;               // 0..31
            int nc = (f & 15) * 4;         // 0..60
            float4 v = *(const float4*)&W[(size_t)(k0 + kk) * H3 + n0 + nc];
            *(float4*)&sB[kk][nc] = v;
        }
        __syncthreads();

        #pragma unroll
        for (int k = 0; k < 32; k++) {
            const ull* bp = (const ull*)&sB[k][tx * 4];
            ull b01 = bp[0];
            ull b23 = bp[1];
            ull a0 = pack2(sA[ty * 4 + 0][k]);
            ull a1 = pack2(sA[ty * 4 + 1][k]);
            ull a2 = pack2(sA[ty * 4 + 2][k]);
            ull a3 = pack2(sA[ty * 4 + 3][k]);
            fma2(acc2[0][0], a0, b01); fma2(acc2[0][1], a0, b23);
            fma2(acc2[1][0], a1, b01); fma2(acc2[1][1], a1, b23);
            fma2(acc2[2][0], a2, b01); fma2(acc2[2][1], a2, b23);
            fma2(acc2[3][0], a3, b01); fma2(acc2[3][1], a3, b23);
        }
        __syncthreads();
    }

    float* xw = g_xw + ((size_t)dir * TT * BB + m0) * H3;
    #pragma unroll
    for (int i = 0; i < 4; i++) {
        int m = ty * 4 + i;
        int n = n0 + tx * 4;
        float2 p01 = unpack2(acc2[i][0]);
        float2 p23 = unpack2(acc2[i][1]);
        float4 o;
        o.x = p01.x + bi[n + 0];
        o.y = p01.y + bi[n + 1];
        o.z = p23.x + bi[n + 2];
        o.w = p23.y + bi[n + 3];
        *(float4*)&xw[(size_t)m * H3 + n] = o;
    }
}

// ---------------------------------------------------------------------------
// Persistent GRU scan kernel (FFMA2 inner loop).
// Grid = 128 CTAs (1/SM). CTA c: dir = c>>6, hidden-column block
// j0 = (c&63)*16. U slice (3 gates x 1024 k x 16 j = 192KB fp32) staged into
// SMEM once. Each timestep: stage h chunk transposed [k][b] (L1-bypassed),
// batch-pair FFMA2 accumulation, gates, write h + output, grid barrier.
// ---------------------------------------------------------------------------
#define SMEM_BYTES ((3 * 1024 * 16 + 64 * 64) * 4)

__global__ __launch_bounds__(256, 1) void gru_persistent(
    const float* __restrict__ Uf, const float* __restrict__ bf,
    const float* __restrict__ Ub, const float* __restrict__ bb,
    float* __restrict__ out)
{
    extern __shared__ float smem[];
    float* sU = smem;                    // [gate][k][16 j]
    float* sH = smem + 3 * 1024 * 16;    // [64 k][64 b]  (transposed chunk)

    const int cta  = blockIdx.x;         // 0..127
    const int dir  = cta >> 6;
    const int j0   = (cta & 63) * 16;

    const float* __restrict__ U    = dir ? Ub : Uf;
    const float* __restrict__ bias = dir ? bb : bf;

    const int tid = threadIdx.x;         // 256
    const int jl  = tid & 15;
    const int bq  = tid >> 4;            // 0..15
    const int j   = j0 + jl;
    const int b0  = bq * 4;

    // ---- Stage this CTA's U slice into SMEM (once) ----
    for (int i = tid; i < 3 * 1024 * 4; i += 256) {
        int g  = i >> 12;                // gate 0..2
        int k  = (i >> 2) & 1023;
        int c  = (i & 3) * 4;
        float4 v = *(const float4*)&U[(size_t)k * H3 + g * HH + j0 + c];
        *(float4*)&sU[((g << 10) + k) * 16 + c] = v;
    }
    const float brz = bias[H3 + j];
    const float brr = bias[H3 + HH + j];
    const float brh = bias[H3 + 2 * HH + j];
    __syncthreads();

    const int bld = tid & 63;            // staging: batch row
    const int kld = (tid >> 6) * 16;     // staging: k group base

    unsigned int bar_target = 0;

    for (int s = 0; s < TT; s++) {
        const int p  = s & 1;
        const int tt = dir ? (TT - 1 - s) : s;
        const float* __restrict__ hp = &g_h[dir][p][0][0];
        float* __restrict__ hn       = &g_h[dir][p ^ 1][0][0];
        const float* __restrict__ xw = g_xw + ((size_t)dir * TT + tt) * BB * H3;

        // Prefetch xw slice and h_prev for this thread's (4 b, 1 j)
        float xz[4], xr[4], xh[4], hprev[4];
        #pragma unroll
        for (int i = 0; i < 4; i++) {
            const float* xwb = xw + (size_t)(b0 + i) * H3;
            xz[i]    = xwb[j];
            xr[i]    = xwb[HH + j];
            xh[i]    = xwb[2 * HH + j];
            hprev[i] = __ldcv(&hp[(size_t)(b0 + i) * HH + j]);   // L1-bypass
        }

        ull azA = 0, azB = 0, arA = 0, arB = 0, ahA = 0, ahB = 0;

        for (int k0 = 0; k0 < HH; k0 += 64) {
            // Stage h chunk transposed to [k][b], coalesced L1-bypassed loads
            {
                const float* src = hp + (size_t)bld * HH + k0 + kld;
                #pragma unroll
                for (int q = 0; q < 4; q++) {
                    float4 v = __ldcv((const float4*)(src + q * 4));
                    int kr = kld + q * 4;
                    sH[(kr + 0) * 64 + bld] = v.x;
                    sH[(kr + 1) * 64 + bld] = v.y;
                    sH[(kr + 2) * 64 + bld] = v.z;
                    sH[(kr + 3) * 64 + bld] = v.w;
                }
            }
            __syncthreads();

            const float* uzp = &sU[(0 * 1024 + k0) * 16 + jl];
            const float* urp = &sU[(1 * 1024 + k0) * 16 + jl];
            const float* uhp = &sU[(2 * 1024 + k0) * 16 + jl];
            const float* sHb = sH + b0;

            #pragma unroll 8
            for (int kk = 0; kk < 64; kk++) {
                ull uz = pack2(uzp[kk * 16]);
                ull ur = pack2(urp[kk * 16]);
                ull uh = pack2(uhp[kk * 16]);
                const ull* hrow = (const ull*)(sHb + kk * 64);
                ull h01 = hrow[0];
                ull h23 = hrow[1];
                fma2(azA, h01, uz); fma2(azB, h23, uz);
                fma2(arA, h01, ur); fma2(arB, h23, ur);
                fma2(ahA, h01, uh); fma2(ahB, h23, uh);
            }
            __syncthreads();
        }

        float az[4], ar[4], ah[4];
        { float2 t0 = unpack2(azA), t1 = unpack2(azB);
          az[0]=t0.x; az[1]=t0.y; az[2]=t1.x; az[3]=t1.y; }
        { float2 t0 = unpack2(arA), t1 = unpack2(arB);
          ar[0]=t0.x; ar[1]=t0.y; ar[2]=t1.x; ar[3]=t1.y; }
        { float2 t0 = unpack2(ahA), t1 = unpack2(ahB);
          ah[0]=t0.x; ah[1]=t0.y; ah[2]=t1.x; ah[3]=t1.y; }

        // Gates + writes
        #pragma unroll
        for (int i = 0; i < 4; i++) {
            int b = b0 + i;
            float z    = 1.f / (1.f + __expf(-(xz[i] + az[i] + brz)));
            float r    = 1.f / (1.f + __expf(-(xr[i] + ar[i] + brr)));
            float cand = tanhf(xh[i] + r * (ah[i] + brh));
            float v    = z * hprev[i] + (1.f - z) * cand;
            hn[(size_t)b * HH + j] = v;
            out[((size_t)b * TT + tt) * (2 * HH) + dir * HH + j] = v;
            if (s == TT - 1)
                out[(size_t)BB * TT * 2 * HH + ((size_t)dir * BB + b) * HH + j] = v;
        }

        // ---- Grid barrier (per direction) ----
        __syncthreads();                     // all CTA threads done writing
        bar_target += 64;
        if (tid == 0) {
            __threadfence();                 // release h writes to L2
            atomicAdd(&g_bar[dir], 1u);
            while (*(volatile unsigned int*)&g_bar[dir] < bar_target) {
                __nanosleep(32);
            }
            __threadfence();                 // acquire
        }
        __syncthreads();
    }
}

// ---------------------------------------------------------------------------
// Launch. Inputs (metadata order): x, hidden, emb, Wf, Uf, bf, Wb, Ub, bb.
// Output: concat (B,T,2H) then hf (B,H) then hb (B,H), all float32.
// ---------------------------------------------------------------------------
extern "C" void kernel_launch(void* const* d_in, const int* in_sizes, int n_in,
                              void* d_out, int out_size)
{
    const int*   x      = (const int*)  d_in[0];
    const float* hidden = (const float*)d_in[1];
    const float* emb    = (const float*)d_in[2];
    const float* Wf     = (const float*)d_in[3];
    const float* Uf     = (const float*)d_in[4];
    const float* bf     = (const float*)d_in[5];
    const float* Wb     = (const float*)d_in[6];
    const float* Ub     = (const float*)d_in[7];
    const float* bb     = (const float*)d_in[8];
    float* out = (float*)d_out;

    cudaFuncSetAttribute(gru_persistent,
                         cudaFuncAttributeMaxDynamicSharedMemorySize, SMEM_BYTES);

    // Init hidden states + barrier counters
    init_h_kernel<<<(2 * BB * HH) / 256, 256>>>(hidden);

    // Input projections for both directions
    {
        dim3 grid(H3 / 64, (TT * BB) / 64, 2);
        input_proj_kernel<<<grid, 256>>>(x, emb, Wf, bf, Wb, bb);
    }

    // Persistent scan: one kernel, 256 internal steps with grid barriers
    gru_persistent<<<128, 256, SMEM_BYTES>>>(Uf, bf, Ub, bb, out);
}

// round 6
// speedup vs baseline: 1.0007x; 1.0007x over previous
#include <cuda_runtime.h>
#include <math.h>

#define BB   64
#define TT   256
#define EE   256
#define HH   1024
#define H3   3072

// Scratch: input projections xw[dir][t][b][j] (includes input bias), ~402MB
__device__ float g_xw[(size_t)2 * TT * BB * H3];
// Hidden state ping-pong: [dir][parity][b][j]
__device__ float g_h[2][2][BB][HH];
// Grid barrier counters, one per direction (monotonic within a launch)
__device__ unsigned int g_bar[2];

// ---------------------------------------------------------------------------
// Packed f32x2 helpers (sm_103a FFMA2 path — ptxas never emits from C++)
// ---------------------------------------------------------------------------
typedef unsigned long long ull;

static __device__ __forceinline__ void fma2(ull& d, ull a, ull b) {
    asm("fma.rn.f32x2 %0, %1, %2, %0;" : "+l"(d) : "l"(a), "l"(b));
}
static __device__ __forceinline__ ull pack2(float x) {
    ull d;
    unsigned int u = __float_as_uint(x);
    asm("mov.b64 %0, {%1, %1};" : "=l"(d) : "r"(u));
    return d;
}
static __device__ __forceinline__ float2 unpack2(ull v) {
    unsigned int lo, hi;
    asm("mov.b64 {%0, %1}, %2;" : "=r"(lo), "=r"(hi) : "l"(v));
    float2 r; r.x = __uint_as_float(lo); r.y = __uint_as_float(hi);
    return r;
}

// ---------------------------------------------------------------------------
// Init hidden state for both directions + reset barrier counters
// ---------------------------------------------------------------------------
__global__ __launch_bounds__(256) void init_h_kernel(const float* __restrict__ hidden) {
    int i = blockIdx.x * blockDim.x + threadIdx.x;   // 0 .. 2*B*H-1
    if (i == 0) { g_bar[0] = 0u; g_bar[1] = 0u; }
    int dir = i / (BB * HH);
    int r   = i % (BB * HH);
    g_h[dir][0][r / HH][r % HH] = hidden[r];
}

// ---------------------------------------------------------------------------
// Fused embedding + input projection GEMM (FFMA2 inner loop):
//   xw[dir][t][b][j] = sum_e emb[x[b][t]][e] * W[e][j] + bi[j]
// M = T*B (row m = t*64+b), N = 3072, K = 256. Tile 64x64, K-chunk 32.
// ---------------------------------------------------------------------------
__global__ __launch_bounds__(256) void input_proj_kernel(
    const int* __restrict__ x, const float* __restrict__ emb,
    const float* __restrict__ Wf, const float* __restrict__ bf,
    const float* __restrict__ Wb, const float* __restrict__ bb)
{
    const int dir = blockIdx.z;
    const float* __restrict__ W  = dir ? Wb : Wf;
    const float* __restrict__ bi = dir ? bb : bf;   // row 0 of b = input bias

    const int m0 = blockIdx.y * 64;
    const int n0 = blockIdx.x * 64;

    __shared__ float sA[64][32];   // [m][k]
    __shared__ float sB[32][64];   // [k][n]
    __shared__ int   sRow[64];

    const int tid = threadIdx.x;
    if (tid < 64) {
        int m = m0 + tid;
        int t = m >> 6;
        int b = m & 63;
        sRow[tid] = x[b * TT + t];
    }
    __syncthreads();

    const int ty = tid >> 4;       // 0..15
    const int tx = tid & 15;       // 0..15

    ull acc2[4][2];
    #pragma unroll
    for (int i = 0; i < 4; i++) { acc2[i][0] = 0ull; acc2[i][1] = 0ull; }

    for (int k0 = 0; k0 < EE; k0 += 32) {
        #pragma unroll
        for (int r = 0; r < 2; r++) {
            int f  = tid + r * 256;        // 0..511
            int m  = f >> 3;               // 0..63
            int kc = (f & 7) * 4;          // 0..28
            float4 v = *(const float4*)&emb[(size_t)sRow[m] * EE + k0 + kc];
            *(float4*)&sA[m][kc] = v;
        }
        #pragma unroll
        for (int r = 0; r < 2; r++) {
            int f  = tid + r * 256;
            int kk = f >> 4;               // 0..31
            int nc = (f & 15) * 4;         // 0..60
            float4 v = *(const float4*)&W[(size_t)(k0 + kk) * H3 + n0 + nc];
            *(float4*)&sB[kk][nc] = v;
        }
        __syncthreads();

        #pragma unroll
        for (int k = 0; k < 32; k++) {
            const ull* bp = (const ull*)&sB[k][tx * 4];
            ull b01 = bp[0];
            ull b23 = bp[1];
            ull a0 = pack2(sA[ty * 4 + 0][k]);
            ull a1 = pack2(sA[ty * 4 + 1][k]);
            ull a2 = pack2(sA[ty * 4 + 2][k]);
            ull a3 = pack2(sA[ty * 4 + 3][k]);
            fma2(acc2[0][0], a0, b01); fma2(acc2[0][1], a0, b23);
            fma2(acc2[1][0], a1, b01); fma2(acc2[1][1], a1, b23);
            fma2(acc2[2][0], a2, b01); fma2(acc2[2][1], a2, b23);
            fma2(acc2[3][0], a3, b01); fma2(acc2[3][1], a3, b23);
        }
        __syncthreads();
    }

    float* xw = g_xw + ((size_t)dir * TT * BB + m0) * H3;
    #pragma unroll
    for (int i = 0; i < 4; i++) {
        int m = ty * 4 + i;
        int n = n0 + tx * 4;
        float2 p01 = unpack2(acc2[i][0]);
        float2 p23 = unpack2(acc2[i][1]);
        float4 o;
        o.x = p01.x + bi[n + 0];
        o.y = p01.y + bi[n + 1];
        o.z = p23.x + bi[n + 2];
        o.w = p23.y + bi[n + 3];
        *(float4*)&xw[(size_t)m * H3 + n] = o;
    }
}

// ---------------------------------------------------------------------------
// Persistent GRU scan kernel (FFMA2 inner loop).
// Grid = 128 CTAs (1/SM). CTA c: dir = c>>6, hidden-column block
// j0 = (c&63)*16. U slice (3 gates x 1024 k x 16 j = 192KB fp32) staged into
// SMEM once. Each timestep: stage h chunk transposed [k][b] (L1-bypassed),
// batch-pair FFMA2 accumulation, gates, write h + output, grid barrier.
// ---------------------------------------------------------------------------
#define SMEM_BYTES ((3 * 1024 * 16 + 64 * 64) * 4)

__global__ __launch_bounds__(256, 1) void gru_persistent(
    const float* __restrict__ Uf, const float* __restrict__ bf,
    const float* __restrict__ Ub, const float* __restrict__ bb,
    float* __restrict__ out)
{
    extern __shared__ float smem[];
    float* sU = smem;                    // [gate][k][16 j]
    float* sH = smem + 3 * 1024 * 16;    // [64 k][64 b]  (transposed chunk)

    const int cta  = blockIdx.x;         // 0..127
    const int dir  = cta >> 6;
    const int j0   = (cta & 63) * 16;

    const float* __restrict__ U    = dir ? Ub : Uf;
    const float* __restrict__ bias = dir ? bb : bf;

    const int tid = threadIdx.x;         // 256
    const int jl  = tid & 15;
    const int bq  = tid >> 4;            // 0..15
    const int j   = j0 + jl;
    const int b0  = bq * 4;

    // ---- Stage this CTA's U slice into SMEM (once) ----
    for (int i = tid; i < 3 * 1024 * 4; i += 256) {
        int g  = i >> 12;                // gate 0..2
        int k  = (i >> 2) & 1023;
        int c  = (i & 3) * 4;
        float4 v = *(const float4*)&U[(size_t)k * H3 + g * HH + j0 + c];
        *(float4*)&sU[((g << 10) + k) * 16 + c] = v;
    }
    const float brz = bias[H3 + j];
    const float brr = bias[H3 + HH + j];
    const float brh = bias[H3 + 2 * HH + j];
    __syncthreads();

    const int bld = tid & 63;            // staging: batch row
    const int kld = (tid >> 6) * 16;     // staging: k group base

    unsigned int bar_target = 0;

    for (int s = 0; s < TT; s++) {
        const int p  = s & 1;
        const int tt = dir ? (TT - 1 - s) : s;
        const float* __restrict__ hp = &g_h[dir][p][0][0];
        float* __restrict__ hn       = &g_h[dir][p ^ 1][0][0];
        const float* __restrict__ xw = g_xw + ((size_t)dir * TT + tt) * BB * H3;

        // Prefetch xw slice and h_prev for this thread's (4 b, 1 j)
        float xz[4], xr[4], xh[4], hprev[4];
        #pragma unroll
        for (int i = 0; i < 4; i++) {
            const float* xwb = xw + (size_t)(b0 + i) * H3;
            xz[i]    = xwb[j];
            xr[i]    = xwb[HH + j];
            xh[i]    = xwb[2 * HH + j];
            hprev[i] = __ldcv(&hp[(size_t)(b0 + i) * HH + j]);   // L1-bypass
        }

        ull azA = 0, azB = 0, arA = 0, arB = 0, ahA = 0, ahB = 0;

        for (int k0 = 0; k0 < HH; k0 += 64) {
            // Stage h chunk transposed to [k][b], coalesced L1-bypassed loads
            {
                const float* src = hp + (size_t)bld * HH + k0 + kld;
                #pragma unroll
                for (int q = 0; q < 4; q++) {
                    float4 v = __ldcv((const float4*)(src + q * 4));
                    int kr = kld + q * 4;
                    sH[(kr + 0) * 64 + bld] = v.x;
                    sH[(kr + 1) * 64 + bld] = v.y;
                    sH[(kr + 2) * 64 + bld] = v.z;
                    sH[(kr + 3) * 64 + bld] = v.w;
                }
            }
            __syncthreads();

            const float* uzp = &sU[(0 * 1024 + k0) * 16 + jl];
            const float* urp = &sU[(1 * 1024 + k0) * 16 + jl];
            const float* uhp = &sU[(2 * 1024 + k0) * 16 + jl];
            const float* sHb = sH + b0;

            #pragma unroll 8
            for (int kk = 0; kk < 64; kk++) {
                ull uz = pack2(uzp[kk * 16]);
                ull ur = pack2(urp[kk * 16]);
                ull uh = pack2(uhp[kk * 16]);
                const ull* hrow = (const ull*)(sHb + kk * 64);
                ull h01 = hrow[0];
                ull h23 = hrow[1];
                fma2(azA, h01, uz); fma2(azB, h23, uz);
                fma2(arA, h01, ur); fma2(arB, h23, ur);
                fma2(ahA, h01, uh); fma2(ahB, h23, uh);
            }
            __syncthreads();
        }

        float az[4], ar[4], ah[4];
        { float2 t0 = unpack2(azA), t1 = unpack2(azB);
          az[0]=t0.x; az[1]=t0.y; az[2]=t1.x; az[3]=t1.y; }
        { float2 t0 = unpack2(arA), t1 = unpack2(arB);
          ar[0]=t0.x; ar[1]=t0.y; ar[2]=t1.x; ar[3]=t1.y; }
        { float2 t0 = unpack2(ahA), t1 = unpack2(ahB);
          ah[0]=t0.x; ah[1]=t0.y; ah[2]=t1.x; ah[3]=t1.y; }

        // Gates + writes
        #pragma unroll
        for (int i = 0; i < 4; i++) {
            int b = b0 + i;
            float z    = 1.f / (1.f + __expf(-(xz[i] + az[i] + brz)));
            float r    = 1.f / (1.f + __expf(-(xr[i] + ar[i] + brr)));
            float cand = tanhf(xh[i] + r * (ah[i] + brh));
            float v    = z * hprev[i] + (1.f - z) * cand;
            hn[(size_t)b * HH + j] = v;
            out[((size_t)b * TT + tt) * (2 * HH) + dir * HH + j] = v;
            if (s == TT - 1)
                out[(size_t)BB * TT * 2 * HH + ((size_t)dir * BB + b) * HH + j] = v;
        }

        // ---- Grid barrier (per direction) ----
        __syncthreads();                     // all CTA threads done writing
        bar_target += 64;
        if (tid == 0) {
            __threadfence();                 // release h writes to L2
            atomicAdd(&g_bar[dir], 1u);
            while (*(volatile unsigned int*)&g_bar[dir] < bar_target) {
                __nanosleep(32);
            }
            __threadfence();                 // acquire
        }
        __syncthreads();
    }
}

// ---------------------------------------------------------------------------
// Launch. Inputs (metadata order): x, hidden, emb, Wf, Uf, bf, Wb, Ub, bb.
// Output: concat (B,T,2H) then hf (B,H) then hb (B,H), all float32.
// ---------------------------------------------------------------------------
extern "C" void kernel_launch(void* const* d_in, const int* in_sizes, int n_in,
                              void* d_out, int out_size)
{
    const int*   x      = (const int*)  d_in[0];
    const float* hidden = (const float*)d_in[1];
    const float* emb    = (const float*)d_in[2];
    const float* Wf     = (const float*)d_in[3];
    const float* Uf     = (const float*)d_in[4];
    const float* bf     = (const float*)d_in[5];
    const float* Wb     = (const float*)d_in[6];
    const float* Ub     = (const float*)d_in[7];
    const float* bb     = (const float*)d_in[8];
    float* out = (float*)d_out;

    cudaFuncSetAttribute(gru_persistent,
                         cudaFuncAttributeMaxDynamicSharedMemorySize, SMEM_BYTES);

    // Init hidden states + barrier counters
    init_h_kernel<<<(2 * BB * HH) / 256, 256>>>(hidden);

    // Input projections for both directions
    {
        dim3 grid(H3 / 64, (TT * BB) / 64, 2);
        input_proj_kernel<<<grid, 256>>>(x, emb, Wf, bf, Wb, bb);
    }

    // Persistent scan: one kernel, 256 internal steps with grid barriers
    gru_persistent<<<128, 256, SMEM_BYTES>>>(Uf, bf, Ub, bb, out);
}

// round 7
// speedup vs baseline: 1.3331x; 1.3322x over previous
#include <cuda_runtime.h>
#include <math.h>

#define BB   64
#define TT   256
#define EE   256
#define HH   1024
#define H3   3072

// Scratch: input projections xw[dir][t][b][j] (includes input bias), ~402MB
__device__ float g_xw[(size_t)2 * TT * BB * H3];
// Hidden state ping-pong: [dir][parity][b][j]
__device__ float g_h[2][2][BB][HH];
// Grid barrier counters, one per direction (monotonic within a launch)
__device__ unsigned int g_bar[2];

// ---------------------------------------------------------------------------
// Init hidden state for both directions + reset barrier counters
// ---------------------------------------------------------------------------
__global__ __launch_bounds__(256) void init_h_kernel(const float* __restrict__ hidden) {
    int i = blockIdx.x * blockDim.x + threadIdx.x;   // 0 .. 2*B*H-1
    if (i == 0) { g_bar[0] = 0u; g_bar[1] = 0u; }
    int dir = i / (BB * HH);
    int r   = i % (BB * HH);
    g_h[dir][0][r / HH][r % HH] = hidden[r];
}

// ---------------------------------------------------------------------------
// Fused embedding + input projection GEMM:
//   xw[dir][t][b][j] = sum_e emb[x[b][t]][e] * W[e][j] + bi[j]
// M = T*B (row m = t*64+b), N = 3072, K = 256.
// Tile 128(M) x 64(N), K-chunk 16, 256 threads, 8x4 microtile,
// register-prefetch software pipeline over K chunks.
// ---------------------------------------------------------------------------
#define SA_STRIDE 132   // padded m-stride for sA[k][m] (4-float aligned, low-conflict)

__global__ __launch_bounds__(256) void input_proj_kernel(
    const int* __restrict__ x, const float* __restrict__ emb,
    const float* __restrict__ Wf, const float* __restrict__ bf,
    const float* __restrict__ Wb, const float* __restrict__ bb)
{
    const int dir = blockIdx.z;
    const float* __restrict__ W  = dir ? Wb : Wf;
    const float* __restrict__ bi = dir ? bb : bf;   // row 0 of b = input bias

    const int m0 = blockIdx.y * 128;
    const int n0 = blockIdx.x * 64;

    __shared__ float sA[16][SA_STRIDE];  // [k][m], m-padded
    __shared__ float sB[16][64];         // [k][n]
    __shared__ int   sRow[128];

    const int tid = threadIdx.x;
    if (tid < 128) {
        int m = m0 + tid;
        int t = m >> 6;
        int b = m & 63;
        sRow[tid] = x[b * TT + t];
    }
    __syncthreads();

    // Staging index mapping (A): idx = tid + r*256, r=0..1  -> 512 float4
    //   m = idx>>2 (0..127), kq = (idx&3)*4
    const int am0 = (tid + 0)   >> 2;
    const int akq0 = ((tid + 0)   & 3) * 4;
    const int am1 = (tid + 256) >> 2;
    const int akq1 = ((tid + 256) & 3) * 4;
    // Staging index mapping (B): kk = tid>>4, nc = (tid&15)*4
    const int bkk = tid >> 4;
    const int bnc = (tid & 15) * 4;

    const int ty = tid >> 4;       // 0..15 -> m-oct
    const int tx = tid & 15;       // 0..15 -> n-quad

    float acc[8][4] = {};
    float4 rA0, rA1, rB;

    // Prefetch chunk 0 into registers
    rA0 = *(const float4*)&emb[(size_t)sRow[am0] * EE + akq0];
    rA1 = *(const float4*)&emb[(size_t)sRow[am1] * EE + akq1];
    rB  = *(const float4*)&W[(size_t)bkk * H3 + n0 + bnc];

    for (int kc = 0; kc < 16; kc++) {
        __syncthreads();   // smem free from previous compute
        // Store registers -> smem
        sA[akq0 + 0][am0] = rA0.x;
        sA[akq0 + 1][am0] = rA0.y;
        sA[akq0 + 2][am0] = rA0.z;
        sA[akq0 + 3][am0] = rA0.w;
        sA[akq1 + 0][am1] = rA1.x;
        sA[akq1 + 1][am1] = rA1.y;
        sA[akq1 + 2][am1] = rA1.z;
        sA[akq1 + 3][am1] = rA1.w;
        *(float4*)&sB[bkk][bnc] = rB;
        __syncthreads();   // smem ready

        // Prefetch next chunk while computing this one
        if (kc < 15) {
            int k0 = (kc + 1) * 16;
            rA0 = *(const float4*)&emb[(size_t)sRow[am0] * EE + k0 + akq0];
            rA1 = *(const float4*)&emb[(size_t)sRow[am1] * EE + k0 + akq1];
            rB  = *(const float4*)&W[(size_t)(k0 + bkk) * H3 + n0 + bnc];
        }

        #pragma unroll
        for (int k = 0; k < 16; k++) {
            float4 alo = *(const float4*)&sA[k][ty * 8];
            float4 ahi = *(const float4*)&sA[k][ty * 8 + 4];
            float4 bv  = *(const float4*)&sB[k][tx * 4];
            float a[8] = {alo.x, alo.y, alo.z, alo.w, ahi.x, ahi.y, ahi.z, ahi.w};
            #pragma unroll
            for (int i = 0; i < 8; i++) {
                acc[i][0] += a[i] * bv.x;
                acc[i][1] += a[i] * bv.y;
                acc[i][2] += a[i] * bv.z;
                acc[i][3] += a[i] * bv.w;
            }
        }
    }

    float* xw = g_xw + ((size_t)dir * TT * BB + m0) * H3;
    const int n = n0 + tx * 4;
    const float bi0 = bi[n + 0], bi1 = bi[n + 1], bi2 = bi[n + 2], bi3 = bi[n + 3];
    #pragma unroll
    for (int i = 0; i < 8; i++) {
        int m = ty * 8 + i;
        float4 o;
        o.x = acc[i][0] + bi0;
        o.y = acc[i][1] + bi1;
        o.z = acc[i][2] + bi2;
        o.w = acc[i][3] + bi3;
        *(float4*)&xw[(size_t)m * H3 + n] = o;
    }
}

// ---------------------------------------------------------------------------
// Persistent GRU scan kernel (R3 form — measured at 93% of fp32 FFMA roofline).
// Grid = 128 CTAs (1/SM). CTA c: dir = c>>6, hidden-column block j0=(c&63)*16.
// U slice (3 gates x 1024 k x 16 j = 192KB fp32) staged into SMEM once.
// Each timestep: stage h chunk (L1-bypassed), 3-gate dot products, gates,
// write h + output, software grid barrier.
// ---------------------------------------------------------------------------
#define SMEM_BYTES ((3 * 1024 * 16 + 64 * 68) * 4)

__global__ __launch_bounds__(256, 1) void gru_persistent(
    const float* __restrict__ Uf, const float* __restrict__ bf,
    const float* __restrict__ Ub, const float* __restrict__ bb,
    float* __restrict__ out)
{
    extern __shared__ float smem[];
    float* sU = smem;                    // [gate][k][16 j]
    float* sH = smem + 3 * 1024 * 16;    // [64 b][68]  (padded rows of k)

    const int cta  = blockIdx.x;         // 0..127
    const int dir  = cta >> 6;
    const int j0   = (cta & 63) * 16;

    const float* __restrict__ U    = dir ? Ub : Uf;
    const float* __restrict__ bias = dir ? bb : bf;

    const int tid = threadIdx.x;         // 256
    const int jl  = tid & 15;
    const int bq  = tid >> 4;            // 0..15
    const int j   = j0 + jl;
    const int b0  = bq * 4;

    // ---- Stage this CTA's U slice into SMEM (once) ----
    for (int i = tid; i < 3 * 1024 * 4; i += 256) {
        int g  = i >> 12;                // gate 0..2
        int k  = (i >> 2) & 1023;
        int c  = (i & 3) * 4;
        float4 v = *(const float4*)&U[(size_t)k * H3 + g * HH + j0 + c];
        *(float4*)&sU[((g << 10) + k) * 16 + c] = v;
    }
    const float brz = bias[H3 + j];
    const float brr = bias[H3 + HH + j];
    const float brh = bias[H3 + 2 * HH + j];
    __syncthreads();

    const int bld = tid >> 4;            // staging: batch row
    const int kld = (tid & 15) * 4;      // staging: k offset

    unsigned int bar_target = 0;

    for (int s = 0; s < TT; s++) {
        const int p  = s & 1;
        const int tt = dir ? (TT - 1 - s) : s;
        const float* __restrict__ hp = &g_h[dir][p][0][0];
        float* __restrict__ hn       = &g_h[dir][p ^ 1][0][0];
        const float* __restrict__ xw = g_xw + ((size_t)dir * TT + tt) * BB * H3;

        // Prefetch xw slice and h_prev for this thread's (4 b, 1 j)
        float xz[4], xr[4], xh[4], hprev[4];
        #pragma unroll
        for (int i = 0; i < 4; i++) {
            const float* xwb = xw + (size_t)(b0 + i) * H3;
            xz[i]    = xwb[j];
            xr[i]    = xwb[HH + j];
            xh[i]    = xwb[2 * HH + j];
            hprev[i] = __ldcv(&hp[(size_t)(b0 + i) * HH + j]);   // L1-bypass
        }

        float az[4] = {0.f, 0.f, 0.f, 0.f};
        float ar[4] = {0.f, 0.f, 0.f, 0.f};
        float ah[4] = {0.f, 0.f, 0.f, 0.f};

        for (int k0 = 0; k0 < HH; k0 += 64) {
            // Stage h chunk [64 b][64 k] into sH (natural [b][k] layout,
            // coalesced 256B-per-warp loads, L1 bypassed).
            const float* src = hp + k0 + kld;
            #pragma unroll
            for (int r = 0; r < 4; r++) {
                int b = bld + r * 16;
                float4 v = __ldcv((const float4*)(src + (size_t)b * HH));
                *(float4*)&sH[b * 68 + kld] = v;
            }
            __syncthreads();

            const float* uzp = &sU[(0 * 1024 + k0) * 16 + jl];
            const float* urp = &sU[(1 * 1024 + k0) * 16 + jl];
            const float* uhp = &sU[(2 * 1024 + k0) * 16 + jl];
            const float* h0p = &sH[(b0 + 0) * 68];
            const float* h1p = &sH[(b0 + 1) * 68];
            const float* h2p = &sH[(b0 + 2) * 68];
            const float* h3p = &sH[(b0 + 3) * 68];

            #pragma unroll 8
            for (int kk = 0; kk < 64; kk++) {
                float uz = uzp[kk * 16];
                float ur = urp[kk * 16];
                float uh = uhp[kk * 16];
                float h0 = h0p[kk];
                float h1 = h1p[kk];
                float h2 = h2p[kk];
                float h3 = h3p[kk];
                az[0] += h0 * uz; ar[0] += h0 * ur; ah[0] += h0 * uh;
                az[1] += h1 * uz; ar[1] += h1 * ur; ah[1] += h1 * uh;
                az[2] += h2 * uz; ar[2] += h2 * ur; ah[2] += h2 * uh;
                az[3] += h3 * uz; ar[3] += h3 * ur; ah[3] += h3 * uh;
            }
            __syncthreads();
        }

        // Gates + writes
        #pragma unroll
        for (int i = 0; i < 4; i++) {
            int b = b0 + i;
            float z    = 1.f / (1.f + __expf(-(xz[i] + az[i] + brz)));
            float r    = 1.f / (1.f + __expf(-(xr[i] + ar[i] + brr)));
            float cand = tanhf(xh[i] + r * (ah[i] + brh));
            float v    = z * hprev[i] + (1.f - z) * cand;
            hn[(size_t)b * HH + j] = v;
            out[((size_t)b * TT + tt) * (2 * HH) + dir * HH + j] = v;
            if (s == TT - 1)
                out[(size_t)BB * TT * 2 * HH + ((size_t)dir * BB + b) * HH + j] = v;
        }

        // ---- Grid barrier (per direction) ----
        __syncthreads();                     // all CTA threads done writing
        bar_target += 64;
        if (tid == 0) {
            __threadfence();                 // release h writes to L2
            atomicAdd(&g_bar[dir], 1u);
            while (*(volatile unsigned int*)&g_bar[dir] < bar_target) {
                __nanosleep(64);
            }
            __threadfence();                 // acquire
        }
        __syncthreads();
    }
}

// ---------------------------------------------------------------------------
// Launch. Inputs (metadata order): x, hidden, emb, Wf, Uf, bf, Wb, Ub, bb.
// Output: concat (B,T,2H) then hf (B,H) then hb (B,H), all float32.
// ---------------------------------------------------------------------------
extern "C" void kernel_launch(void* const* d_in, const int* in_sizes, int n_in,
                              void* d_out, int out_size)
{
    const int*   x      = (const int*)  d_in[0];
    const float* hidden = (const float*)d_in[1];
    const float* emb    = (const float*)d_in[2];
    const float* Wf     = (const float*)d_in[3];
    const float* Uf     = (const float*)d_in[4];
    const float* bf     = (const float*)d_in[5];
    const float* Wb     = (const float*)d_in[6];
    const float* Ub     = (const float*)d_in[7];
    const float* bb     = (const float*)d_in[8];
    float* out = (float*)d_out;

    cudaFuncSetAttribute(gru_persistent,
                         cudaFuncAttributeMaxDynamicSharedMemorySize, SMEM_BYTES);

    // Init hidden states + barrier counters
    init_h_kernel<<<(2 * BB * HH) / 256, 256>>>(hidden);

    // Input projections for both directions
    {
        dim3 grid(H3 / 64, (TT * BB) / 128, 2);
        input_proj_kernel<<<grid, 256>>>(x, emb, Wf, bf, Wb, bb);
    }

    // Persistent scan: one kernel, 256 internal steps with grid barriers
    gru_persistent<<<128, 256, SMEM_BYTES>>>(Uf, bf, Ub, bb, out);
}

// round 8
// speedup vs baseline: 1.9584x; 1.4691x over previous
#include <cuda_runtime.h>
#include <cuda_bf16.h>
#include <math.h>
#include <stdint.h>

#define BB   64
#define TT   256
#define EE   256
#define HH   1024
#define H3   3072

// Scratch: input projections xw[dir][t][b][j] (includes input bias), ~402MB
__device__ float g_xw[(size_t)2 * TT * BB * H3];
// Hidden state ping-pong: [dir][parity][b][j]
__device__ float g_h[2][2][BB][HH];
// Grid barrier counters, one per direction (monotonic within a launch)
__device__ unsigned int g_bar[2];

typedef unsigned long long ull;

// ---------------------------------------------------------------------------
// bf16 split helpers
// ---------------------------------------------------------------------------
static __device__ __forceinline__ unsigned pack_bf16(float a, float b) {
    unsigned short sa = __bfloat16_as_ushort(__float2bfloat16(a));
    unsigned short sb = __bfloat16_as_ushort(__float2bfloat16(b));
    return (unsigned)sa | ((unsigned)sb << 16);
}
static __device__ __forceinline__ float bf16_hi(float a) {
    return __bfloat162float(__float2bfloat16(a));
}

// ---------------------------------------------------------------------------
// MMA / ldmatrix wrappers
// ---------------------------------------------------------------------------
static __device__ __forceinline__ void mma_bf16(float* c, const unsigned* a,
                                                unsigned b0, unsigned b1) {
    asm("mma.sync.aligned.m16n8k16.row.col.f32.bf16.bf16.f32 "
        "{%0,%1,%2,%3}, {%4,%5,%6,%7}, {%8,%9}, {%0,%1,%2,%3};"
        : "+f"(c[0]), "+f"(c[1]), "+f"(c[2]), "+f"(c[3])
        : "r"(a[0]), "r"(a[1]), "r"(a[2]), "r"(a[3]), "r"(b0), "r"(b1));
}
static __device__ __forceinline__ void ldm_x4(unsigned* d, uint32_t addr) {
    asm volatile("ldmatrix.sync.aligned.m8n8.x4.shared.b16 {%0,%1,%2,%3}, [%4];"
        : "=r"(d[0]), "=r"(d[1]), "=r"(d[2]), "=r"(d[3]) : "r"(addr));
}

// ---------------------------------------------------------------------------
// Init hidden state for both directions + reset barrier counters
// ---------------------------------------------------------------------------
__global__ __launch_bounds__(256) void init_h_kernel(const float* __restrict__ hidden) {
    int i = blockIdx.x * blockDim.x + threadIdx.x;   // 0 .. 2*B*H-1
    if (i == 0) { g_bar[0] = 0u; g_bar[1] = 0u; }
    int dir = i / (BB * HH);
    int r   = i % (BB * HH);
    g_h[dir][0][r / HH][r % HH] = hidden[r];
}

// ---------------------------------------------------------------------------
// Fused embedding + input projection GEMM (unchanged from R7).
// ---------------------------------------------------------------------------
#define SA_STRIDE 132

__global__ __launch_bounds__(256) void input_proj_kernel(
    const int* __restrict__ x, const float* __restrict__ emb,
    const float* __restrict__ Wf, const float* __restrict__ bf,
    const float* __restrict__ Wb, const float* __restrict__ bb)
{
    const int dir = blockIdx.z;
    const float* __restrict__ W  = dir ? Wb : Wf;
    const float* __restrict__ bi = dir ? bb : bf;

    const int m0 = blockIdx.y * 128;
    const int n0 = blockIdx.x * 64;

    __shared__ float sA[16][SA_STRIDE];
    __shared__ float sB[16][64];
    __shared__ int   sRow[128];

    const int tid = threadIdx.x;
    if (tid < 128) {
        int m = m0 + tid;
        int t = m >> 6;
        int b = m & 63;
        sRow[tid] = x[b * TT + t];
    }
    __syncthreads();

    const int am0 = (tid + 0)   >> 2;
    const int akq0 = ((tid + 0)   & 3) * 4;
    const int am1 = (tid + 256) >> 2;
    const int akq1 = ((tid + 256) & 3) * 4;
    const int bkk = tid >> 4;
    const int bnc = (tid & 15) * 4;

    const int ty = tid >> 4;
    const int tx = tid & 15;

    float acc[8][4] = {};
    float4 rA0, rA1, rB;

    rA0 = *(const float4*)&emb[(size_t)sRow[am0] * EE + akq0];
    rA1 = *(const float4*)&emb[(size_t)sRow[am1] * EE + akq1];
    rB  = *(const float4*)&W[(size_t)bkk * H3 + n0 + bnc];

    for (int kc = 0; kc < 16; kc++) {
        __syncthreads();
        sA[akq0 + 0][am0] = rA0.x;
        sA[akq0 + 1][am0] = rA0.y;
        sA[akq0 + 2][am0] = rA0.z;
        sA[akq0 + 3][am0] = rA0.w;
        sA[akq1 + 0][am1] = rA1.x;
        sA[akq1 + 1][am1] = rA1.y;
        sA[akq1 + 2][am1] = rA1.z;
        sA[akq1 + 3][am1] = rA1.w;
        *(float4*)&sB[bkk][bnc] = rB;
        __syncthreads();

        if (kc < 15) {
            int k0 = (kc + 1) * 16;
            rA0 = *(const float4*)&emb[(size_t)sRow[am0] * EE + k0 + akq0];
            rA1 = *(const float4*)&emb[(size_t)sRow[am1] * EE + k0 + akq1];
            rB  = *(const float4*)&W[(size_t)(k0 + bkk) * H3 + n0 + bnc];
        }

        #pragma unroll
        for (int k = 0; k < 16; k++) {
            float4 alo = *(const float4*)&sA[k][ty * 8];
            float4 ahi = *(const float4*)&sA[k][ty * 8 + 4];
            float4 bv  = *(const float4*)&sB[k][tx * 4];
            float a[8] = {alo.x, alo.y, alo.z, alo.w, ahi.x, ahi.y, ahi.z, ahi.w};
            #pragma unroll
            for (int i = 0; i < 8; i++) {
                acc[i][0] += a[i] * bv.x;
                acc[i][1] += a[i] * bv.y;
                acc[i][2] += a[i] * bv.z;
                acc[i][3] += a[i] * bv.w;
            }
        }
    }

    float* xw = g_xw + ((size_t)dir * TT * BB + m0) * H3;
    const int n = n0 + tx * 4;
    const float bi0 = bi[n + 0], bi1 = bi[n + 1], bi2 = bi[n + 2], bi3 = bi[n + 3];
    #pragma unroll
    for (int i = 0; i < 8; i++) {
        int m = ty * 8 + i;
        float4 o;
        o.x = acc[i][0] + bi0;
        o.y = acc[i][1] + bi1;
        o.z = acc[i][2] + bi2;
        o.w = acc[i][3] + bi3;
        *(float4*)&xw[(size_t)m * H3 + n] = o;
    }
}

// ---------------------------------------------------------------------------
// Persistent GRU scan kernel — tensor-core (HMMA bf16 split) version.
//
// Grid = 128 CTAs (1/SM). CTA c: dir = c>>6, j0 = (c&63)*16.
// Per-step GEMM: D[64 b][48 col] = h[64][1024] @ Ucta[1024][48]
//   (48 cols = 3 gates x 16 j), via mma.sync.m16n8k16 bf16 with 3-term split
//   Uhi*hhi + Uhi*hlo + Ulo*hhi, fp32 accumulators.
// U is pre-packed ONCE into SMEM in exact B-fragment order.
// h staged per 64-k chunk as bf16 hi/lo (ldmatrix layout), register prefetch.
// 8 warps = 4 m-tiles (16 b) x 2 n-halves (3 ntiles of 8 cols).
// ---------------------------------------------------------------------------
#define SH_PAD   72                       // bf16 elems per sH row (144B, conflict-free ldmatrix)
#define SUF_BYTES (64 * 6 * 32 * 16)      // 196,608
#define SD_FLOATS (64 * 50)               // 12,800 B
#define SD_OFF_F  (SUF_BYTES / 4)         // float index of sD
#define SH_OFF_B  (SUF_BYTES + SD_FLOATS * 4)              // byte offset of sH
#define SCAN_SMEM (SH_OFF_B + 2 * 64 * SH_PAD * 2)         // 227,840 B

__global__ __launch_bounds__(256, 1) void gru_persistent(
    const float* __restrict__ Uf, const float* __restrict__ bf,
    const float* __restrict__ Ub, const float* __restrict__ bb,
    float* __restrict__ out)
{
    extern __shared__ float smem[];
    uint4* sUf = (uint4*)smem;                          // [t64][ntile6][lane32] 16B
    float* sD  = smem + SD_OFF_F;                       // [64 b][50]
    unsigned short* sH = (unsigned short*)((char*)smem + SH_OFF_B); // [2 split][64 b][SH_PAD]

    const int cta  = blockIdx.x;         // 0..127
    const int dir  = cta >> 6;
    const int j0   = (cta & 63) * 16;

    const float* __restrict__ U    = dir ? Ub : Uf;
    const float* __restrict__ bias = dir ? bb : bf;

    const int tid  = threadIdx.x;        // 256
    const int lane = tid & 31;
    const int w    = tid >> 5;           // 0..7
    const int mtile  = w & 3;            // 16-batch-row tile
    const int nhalf  = w >> 2;           // 3 ntiles each

    // Gate-phase thread mapping (same as before)
    const int jl  = tid & 15;
    const int bq  = tid >> 4;            // 0..15
    const int j   = j0 + jl;
    const int b0g = bq * 4;

    // ---- Pre-pack U into B-fragment order (once) ----
    // slot = (t*6 + n)*32 + l ; 16B = {uhi_b0, uhi_b1, ulo_b0, ulo_b1}
    for (int slot = tid; slot < 64 * 6 * 32; slot += 256) {
        int t   = slot / 192;
        int rem = slot % 192;
        int n   = rem >> 5;
        int l   = rem & 31;
        int c    = l & 3;
        int colq = l >> 2;
        int coln = n * 8 + colq;          // 0..47
        int g    = coln >> 4;
        int jc   = coln & 15;
        const float* Ucol = U + (size_t)g * HH + j0 + jc;
        int k0r = t * 16 + 2 * c;
        float u00 = Ucol[(size_t)(k0r + 0) * H3];
        float u01 = Ucol[(size_t)(k0r + 1) * H3];
        float u10 = Ucol[(size_t)(k0r + 8) * H3];
        float u11 = Ucol[(size_t)(k0r + 9) * H3];
        uint4 v;
        v.x = pack_bf16(u00, u01);
        v.y = pack_bf16(u10, u11);
        v.z = pack_bf16(u00 - bf16_hi(u00), u01 - bf16_hi(u01));
        v.w = pack_bf16(u10 - bf16_hi(u10), u11 - bf16_hi(u11));
        sUf[slot] = v;
    }
    const float brz = bias[H3 + j];
    const float brr = bias[H3 + HH + j];
    const float brh = bias[H3 + 2 * HH + j];
    __syncthreads();

    // h staging mapping: thread -> (row b, 16 k starting at kb)
    const int sb = tid >> 2;             // 0..63
    const int kb = (tid & 3) * 16;       // 0,16,32,48

    // ldmatrix base addresses (chunk-k-local part added in loop)
    const int arow_hi = (0 * 64 + mtile * 16 + (lane & 15)) * SH_PAD;
    const int arow_lo = (1 * 64 + mtile * 16 + (lane & 15)) * SH_PAD;
    const int acol    = (lane >> 4) * 8;
    const uint32_t sH_base = (uint32_t)__cvta_generic_to_shared(sH);

    unsigned int bar_target = 0;

    for (int s = 0; s < TT; s++) {
        const int p  = s & 1;
        const int tt = dir ? (TT - 1 - s) : s;
        const float* __restrict__ hp = &g_h[dir][p][0][0];
        float* __restrict__ hn       = &g_h[dir][p ^ 1][0][0];
        const float* __restrict__ xw = g_xw + ((size_t)dir * TT + tt) * BB * H3;

        // Prefetch xw slice and h_prev for this thread's (4 b, 1 j)
        float xz[4], xr[4], xh[4], hprev[4];
        #pragma unroll
        for (int i = 0; i < 4; i++) {
            const float* xwb = xw + (size_t)(b0g + i) * H3;
            xz[i]    = xwb[j];
            xr[i]    = xwb[HH + j];
            xh[i]    = xwb[2 * HH + j];
            hprev[i] = __ldcv(&hp[(size_t)(b0g + i) * HH + j]);
        }

        float acc[3][4] = {};            // D fragments: 3 ntiles x 4 regs

        // Prefetch h chunk 0
        float4 pr[4];
        {
            const float* src = hp + (size_t)sb * HH + kb;
            #pragma unroll
            for (int q = 0; q < 4; q++)
                pr[q] = __ldcv((const float4*)(src + q * 4));
        }

        for (int c = 0; c < 16; c++) {
            __syncthreads();             // previous chunk MMAs done, sH free
            // Convert + store this chunk (bf16 hi / lo)
            #pragma unroll
            for (int q = 0; q < 4; q++) {
                float4 v = pr[q];
                float hx = bf16_hi(v.x), hy = bf16_hi(v.y);
                float hz2 = bf16_hi(v.z), hw = bf16_hi(v.w);
                unsigned hi01 = pack_bf16(v.x, v.y);
                unsigned hi23 = pack_bf16(v.z, v.w);
                unsigned lo01 = pack_bf16(v.x - hx, v.y - hy);
                unsigned lo23 = pack_bf16(v.z - hz2, v.w - hw);
                int e = kb + q * 4;
                *(ull*)&sH[(0 * 64 + sb) * SH_PAD + e] = (ull)hi01 | ((ull)hi23 << 32);
                *(ull*)&sH[(1 * 64 + sb) * SH_PAD + e] = (ull)lo01 | ((ull)lo23 << 32);
            }
            __syncthreads();             // chunk visible

            // Prefetch next chunk while MMAs run
            if (c < 15) {
                const float* src = hp + (size_t)sb * HH + (c + 1) * 64 + kb;
                #pragma unroll
                for (int q = 0; q < 4; q++)
                    pr[q] = __ldcv((const float4*)(src + q * 4));
            }

            // 4 k-steps of 16 in this chunk
            #pragma unroll
            for (int t = 0; t < 4; t++) {
                unsigned ahi[4], alo[4];
                int kc = t * 16 + acol;
                ldm_x4(ahi, sH_base + (uint32_t)(arow_hi + kc) * 2);
                ldm_x4(alo, sH_base + (uint32_t)(arow_lo + kc) * 2);
                int tg = c * 4 + t;
                #pragma unroll
                for (int n = 0; n < 3; n++) {
                    int ntile = nhalf * 3 + n;
                    uint4 bfrag = sUf[(tg * 6 + ntile) * 32 + lane];
                    mma_bf16(acc[n], ahi, bfrag.x, bfrag.y);   // Uhi * hhi
                    mma_bf16(acc[n], alo, bfrag.x, bfrag.y);   // Uhi * hlo
                    mma_bf16(acc[n], ahi, bfrag.z, bfrag.w);   // Ulo * hhi
                }
            }
        }

        // Write D fragments to sD
        {
            int row0 = mtile * 16 + (lane >> 2);
            #pragma unroll
            for (int n = 0; n < 3; n++) {
                int coln = (nhalf * 3 + n) * 8 + 2 * (lane & 3);
                float2 v0 = make_float2(acc[n][0], acc[n][1]);
                float2 v1 = make_float2(acc[n][2], acc[n][3]);
                *(float2*)&sD[row0 * 50 + coln]       = v0;
                *(float2*)&sD[(row0 + 8) * 50 + coln] = v1;
            }
        }
        __syncthreads();

        // Gates + writes
        #pragma unroll
        for (int i = 0; i < 4; i++) {
            int b = b0g + i;
            float az = sD[b * 50 + jl];
            float ar = sD[b * 50 + 16 + jl];
            float ah = sD[b * 50 + 32 + jl];
            float z    = 1.f / (1.f + __expf(-(xz[i] + az + brz)));
            float r    = 1.f / (1.f + __expf(-(xr[i] + ar + brr)));
            float cand = tanhf(xh[i] + r * (ah + brh));
            float v    = z * hprev[i] + (1.f - z) * cand;
            hn[(size_t)b * HH + j] = v;
            out[((size_t)b * TT + tt) * (2 * HH) + dir * HH + j] = v;
            if (s == TT - 1)
                out[(size_t)BB * TT * 2 * HH + ((size_t)dir * BB + b) * HH + j] = v;
        }

        // ---- Grid barrier (per direction) ----
        __syncthreads();
        bar_target += 64;
        if (tid == 0) {
            __threadfence();
            atomicAdd(&g_bar[dir], 1u);
            while (*(volatile unsigned int*)&g_bar[dir] < bar_target) {
                __nanosleep(64);
            }
            __threadfence();
        }
        __syncthreads();
    }
}

// ---------------------------------------------------------------------------
// Launch. Inputs (metadata order): x, hidden, emb, Wf, Uf, bf, Wb, Ub, bb.
// Output: concat (B,T,2H) then hf (B,H) then hb (B,H), all float32.
// ---------------------------------------------------------------------------
extern "C" void kernel_launch(void* const* d_in, const int* in_sizes, int n_in,
                              void* d_out, int out_size)
{
    const int*   x      = (const int*)  d_in[0];
    const float* hidden = (const float*)d_in[1];
    const float* emb    = (const float*)d_in[2];
    const float* Wf     = (const float*)d_in[3];
    const float* Uf     = (const float*)d_in[4];
    const float* bf     = (const float*)d_in[5];
    const float* Wb     = (const float*)d_in[6];
    const float* Ub     = (const float*)d_in[7];
    const float* bb     = (const float*)d_in[8];
    float* out = (float*)d_out;

    cudaFuncSetAttribute(gru_persistent,
                         cudaFuncAttributeMaxDynamicSharedMemorySize, SCAN_SMEM);

    init_h_kernel<<<(2 * BB * HH) / 256, 256>>>(hidden);

    {
        dim3 grid(H3 / 64, (TT * BB) / 128, 2);
        input_proj_kernel<<<grid, 256>>>(x, emb, Wf, bf, Wb, bb);
    }

    gru_persistent<<<128, 256, SCAN_SMEM>>>(Uf, bf, Ub, bb, out);
}